// round 7
// baseline (speedup 1.0000x reference)
#include <cuda_runtime.h>

#define GN    6
#define NN    36
#define NB7   7            // 7x7 counter grid incl. trash row/col
#define NPED  8192
#define HID   128
#define RPB   64           // rows per count block
#define NSL   8            // j-slices
#define JCH   (NPED / NSL) // 1024
#define HB4   (NPED / 4)   // 2048 u32 words per (slice,bin): 4 byte-packed rows/word

// Per-slice byte-packed partial counts: g8[((sl*NN)+c)*HB4 + i/4], byte q = row 4*(i/4)+q.
// Fully overwritten by count_kernel every launch -> no zeroing, replay-safe.
__device__ unsigned g8[NSL * NN * HB4];   // 2.36 MB

// ---------------------------------------------------------------------------
// Phase 1: branch-free occupancy histogram, conflict-free u32 counters.
// Out-of-range pairs land in trash bins (bx==6 or by==6), never flushed.
// ---------------------------------------------------------------------------
__global__ __launch_bounds__(RPB) void count_kernel(const float* __restrict__ obs2) {
    __shared__ unsigned   cnt[NB7 * NB7 * RPB];  // [bin49][t], bank = t%32 (conflict-free)
    __shared__ ulonglong2 pts[JCH / 2];          // 8 KB, 2 points per element

    const int t  = threadIdx.x;
    const int i  = blockIdx.x * RPB + t;
    const int j0 = blockIdx.y * JCH;

    // Stage slice points (128-bit loads)
    {
        const ulonglong2* src = (const ulonglong2*)(obs2 + 2 * j0);
#pragma unroll
        for (int k = 0; k < JCH / 2 / RPB; k++)
            pts[t + k * RPB] = src[t + k * RPB];
    }
#pragma unroll
    for (int k = 0; k < NB7 * NB7; k++)
        cnt[k * RPB + t] = 0u;

    const float2 pi = ((const float2*)obs2)[i];
    float nx = -pi.x, ny = -pi.y;
    unsigned long long negpi;
    asm("mov.b64 %0, {%1,%2};" : "=l"(negpi) : "f"(nx), "f"(ny));
    const unsigned long long THREE2 = 0x4040000040400000ULL;  // (3.0f, 3.0f)
    const float MAGIC = 8388608.0f;                           // 2^23

    __syncthreads();

    unsigned* mycnt = cnt + t;

#pragma unroll 4
    for (int k = 0; k < JCH / 2; k++) {
        const ulonglong2 pp = pts[k];   // LDS.128 broadcast: two points
#pragma unroll
        for (int half = 0; half < 2; half++) {
            const unsigned long long pj = half ? pp.y : pp.x;
            unsigned long long d, e;
            // EXACT reference order per lane: rn(pj - pi), then rn(+3)
            asm("add.rn.f32x2 %0, %1, %2;" : "=l"(d) : "l"(pj), "l"(negpi));
            asm("add.rn.f32x2 %0, %1, %2;" : "=l"(e) : "l"(d), "l"(THREE2));
            const float ex = __uint_as_float((unsigned)e);
            const float ey = __uint_as_float((unsigned)(e >> 32));
            float fx, fy;
            asm("add.rm.f32 %0, %1, %2;" : "=f"(fx) : "f"(ex), "f"(MAGIC));
            asm("add.rm.f32 %0, %1, %2;" : "=f"(fy) : "f"(ey), "f"(MAGIC));
            unsigned bx = __float_as_uint(fx) - 0x4B000000u;  // floor; OOR -> huge
            unsigned by = __float_as_uint(fy) - 0x4B000000u;
            bx = umin(bx, 6u);
            by = umin(by, 6u);
            mycnt[(bx * NB7 + by) * RPB] += 1u;  // conflict-free RMW, no branch
        }
    }

    __syncthreads();  // flush reads other threads' counter columns

    // Flush 36 valid bins, byte-packed 4 rows/word: 36*16 = 576 words, 9/thread.
    // Per-slice counts <= ~105 < 255, so bytes cannot overflow.
    const int sl = blockIdx.y;
#pragma unroll
    for (int k = 0; k < 9; k++) {
        const int gidx = k * RPB + t;     // 0..575
        const int vb   = gidx >> 4;       // valid bin 0..35
        const int w    = gidx & 15;       // word (4 rows) within this i-block
        const int b49  = (vb / GN) * NB7 + (vb % GN);
        const unsigned b0 = cnt[b49 * RPB + 4 * w + 0];
        const unsigned b1 = cnt[b49 * RPB + 4 * w + 1];
        const unsigned b2 = cnt[b49 * RPB + 4 * w + 2];
        const unsigned b3 = cnt[b49 * RPB + 4 * w + 3];
        g8[(sl * NN + vb) * HB4 + blockIdx.x * (RPB / 4) + w] =
            b0 | (b1 << 8) | (b2 << 16) | (b3 << 24);
    }
}

// ---------------------------------------------------------------------------
// Phase 2: reduce slices (uint4 loads, packed-u16 accumulation), remove the
// self pair (always bin 21), register-blocked GEMM (2 h per thread: each cs
// LDS feeds 2 FMAs). 256 blocks x 128 thr, block = 32 rows x 128 h.
// ---------------------------------------------------------------------------
__global__ __launch_bounds__(HID) void embed_kernel(const float* __restrict__ W,
                                                    const float* __restrict__ b,
                                                    float* __restrict__ out) {
    __shared__ float cs[32][NN];   // reduced counts for this block's 32 rows

    const int t  = threadIdx.x;
    const int i0 = blockIdx.x * 32;

    // Phase A: 36 bins x 2 uint4-chunks (16 rows each) = 72 tasks.
    if (t < NN * 2) {
        const int c     = t >> 1;
        const int chunk = t & 1;          // rows chunk*16 .. +15
        const uint4* gv = (const uint4*)g8;
        unsigned acc[8];                  // 16 u16 lanes = 16 rows
#pragma unroll
        for (int q = 0; q < 8; q++) acc[q] = 0u;
#pragma unroll
        for (int sl = 0; sl < NSL; sl++) {
            const uint4 v = gv[(sl * NN + c) * (HB4 / 4) + blockIdx.x * 2 + chunk];
            const unsigned vv[4] = {v.x, v.y, v.z, v.w};
#pragma unroll
            for (int q = 0; q < 4; q++) {
                acc[2 * q + 0] += __byte_perm(vv[q], 0, 0x4140);  // (b0,b1) u16 pair
                acc[2 * q + 1] += __byte_perm(vv[q], 0, 0x4342);  // (b2,b3)
            }
        }
        const unsigned self = (c == 3 * GN + 3) ? 1u : 0u;
#pragma unroll
        for (int q = 0; q < 4; q++) {
            const int rl = chunk * 16 + 4 * q;
            cs[rl + 0][c] = (float)((acc[2 * q]     & 0xFFFFu) - self);
            cs[rl + 1][c] = (float)((acc[2 * q]     >> 16)     - self);
            cs[rl + 2][c] = (float)((acc[2 * q + 1] & 0xFFFFu) - self);
            cs[rl + 3][c] = (float)((acc[2 * q + 1] >> 16)     - self);
        }
    }
    __syncthreads();

    // Phase B: thread = (h pair, row group). h0 = 2*(t%64), rows (t/64)*16..+15.
    const int h0 = (t & 63) * 2;
    const int rg = t >> 6;

    float w[2 * NN];   // W rows h0 and h0+1: 72 consecutive floats = 18 float4
    {
        const float4* Wv = (const float4*)(W + h0 * NN);
#pragma unroll
        for (int q = 0; q < 2 * NN / 4; q++) {
            const float4 v = Wv[q];
            w[4 * q + 0] = v.x; w[4 * q + 1] = v.y;
            w[4 * q + 2] = v.z; w[4 * q + 3] = v.w;
        }
    }
    const float bh0 = b[h0];
    const float bh1 = b[h0 + 1];

#pragma unroll
    for (int r = 0; r < 16; r++) {
        const int row = rg * 16 + r;
        float a0 = bh0, a1 = bh1;
#pragma unroll
        for (int c = 0; c < NN; c++) {
            const float v = cs[row][c];         // broadcast LDS -> 2 FMAs
            a0 = fmaf(v, w[c], a0);
            a1 = fmaf(v, w[NN + c], a1);
        }
        *(float2*)&out[(i0 + row) * HID + h0] = make_float2(a0, a1);
    }
}

// ---------------------------------------------------------------------------
// Inputs: 0 hidden_state (unused), 1 obs1 (unused), 2 obs2 [8192,2],
// 3 W [128,36], 4 b [128]. Output fp32 [8192,128].
// ---------------------------------------------------------------------------
extern "C" void kernel_launch(void* const* d_in, const int* in_sizes, int n_in,
                              void* d_out, int out_size) {
    const float* obs2 = (const float*)d_in[2];
    const float* W    = (const float*)d_in[3];
    const float* b    = (const float*)d_in[4];
    float*       out  = (float*)d_out;

    dim3 g1(NPED / RPB, NSL);        // 128 x 8 = 1024 blocks
    count_kernel<<<g1, RPB>>>(obs2);
    embed_kernel<<<NPED / 32, HID>>>(W, b, out);
}

// round 8
// speedup vs baseline: 1.2053x; 1.2053x over previous
#include <cuda_runtime.h>

#define GN    6
#define NN    36
#define NB7   7            // 7x7 counter grid incl. trash row/col
#define NPED  8192
#define HID   128
#define RPB   128          // rows per count block (proven 28 warps/SM config)
#define NSL   16           // j-slices
#define JCH   (NPED / NSL) // 512
#define HB4   (NPED / 4)   // 2048 u32 words per (slice,bin): 4 byte-packed rows/word

// Per-slice byte-packed partial counts: g8[((sl*NN)+c)*HB4 + i/4], byte q = row i%4.
// Fully overwritten by count_kernel every launch -> no zeroing, replay-safe.
__device__ unsigned g8[NSL * NN * HB4];   // 4.7 MB

// ---------------------------------------------------------------------------
// Phase 1: branch-free occupancy histogram, conflict-free u32 counters.
// Out-of-range pairs land in trash bins (bx==6 or by==6), never flushed.
// ---------------------------------------------------------------------------
__global__ __launch_bounds__(RPB) void count_kernel(const float* __restrict__ obs2) {
    __shared__ unsigned   cnt[NB7 * NB7 * RPB];  // [bin49][t], bank = t%32 (conflict-free)
    __shared__ ulonglong2 pts[JCH / 2];          // 4 KB, 2 points per element

    const int t  = threadIdx.x;
    const int i  = blockIdx.x * RPB + t;
    const int j0 = blockIdx.y * JCH;

    // Stage slice points (128-bit loads)
    {
        const ulonglong2* src = (const ulonglong2*)(obs2 + 2 * j0);
#pragma unroll
        for (int k = 0; k < JCH / 2 / RPB; k++)
            pts[t + k * RPB] = src[t + k * RPB];
    }
#pragma unroll
    for (int k = 0; k < NB7 * NB7; k++)
        cnt[k * RPB + t] = 0u;

    const float2 pi = ((const float2*)obs2)[i];
    float nx = -pi.x, ny = -pi.y;
    unsigned long long negpi;
    asm("mov.b64 %0, {%1,%2};" : "=l"(negpi) : "f"(nx), "f"(ny));
    const unsigned long long THREE2 = 0x4040000040400000ULL;  // (3.0f, 3.0f)
    const float MAGIC = 8388608.0f;                           // 2^23

    __syncthreads();

    unsigned* mycnt = cnt + t;

#pragma unroll 4
    for (int k = 0; k < JCH / 2; k++) {
        const ulonglong2 pp = pts[k];   // LDS.128 broadcast: two points
#pragma unroll
        for (int half = 0; half < 2; half++) {
            const unsigned long long pj = half ? pp.y : pp.x;
            unsigned long long d, e;
            // EXACT reference order per lane: rn(pj - pi), then rn(+3)
            asm("add.rn.f32x2 %0, %1, %2;" : "=l"(d) : "l"(pj), "l"(negpi));
            asm("add.rn.f32x2 %0, %1, %2;" : "=l"(e) : "l"(d), "l"(THREE2));
            const float ex = __uint_as_float((unsigned)e);
            const float ey = __uint_as_float((unsigned)(e >> 32));
            float fx, fy;
            asm("add.rm.f32 %0, %1, %2;" : "=f"(fx) : "f"(ex), "f"(MAGIC));
            asm("add.rm.f32 %0, %1, %2;" : "=f"(fy) : "f"(ey), "f"(MAGIC));
            unsigned bx = __float_as_uint(fx) - 0x4B000000u;  // floor; OOR -> huge
            unsigned by = __float_as_uint(fy) - 0x4B000000u;
            bx = umin(bx, 6u);
            by = umin(by, 6u);
            mycnt[(bx * NB7 + by) * RPB] += 1u;  // conflict-free RMW, no branch
        }
    }

    __syncthreads();  // flush reads other threads' counter columns

    // Flush 36 valid bins, byte-packed 4 rows/word: 36*32 = 1152 words, 9/thread.
    // Per-slice (512 j) bin counts <= ~60 < 255: bytes cannot overflow.
    const int sl = blockIdx.y;
#pragma unroll
    for (int k = 0; k < 9; k++) {
        const int gidx = k * RPB + t;     // 0..1151
        const int vb   = gidx >> 5;       // valid bin 0..35
        const int w    = gidx & 31;       // word (4 rows) within this i-block
        const int b49  = (vb / GN) * NB7 + (vb % GN);
        const unsigned b0 = cnt[b49 * RPB + 4 * w + 0];
        const unsigned b1 = cnt[b49 * RPB + 4 * w + 1];
        const unsigned b2 = cnt[b49 * RPB + 4 * w + 2];
        const unsigned b3 = cnt[b49 * RPB + 4 * w + 3];
        g8[(sl * NN + vb) * HB4 + blockIdx.x * (RPB / 4) + w] =
            b0 | (b1 << 8) | (b2 << 16) | (b3 << 24);
    }
}

// ---------------------------------------------------------------------------
// Phase 2: reduce slices, remove self pair (always bin 21), register-blocked
// GEMM (2 h per thread: each broadcast LDS feeds 2 FMAs).
// 1024 blocks x 128 thr, block = 8 rows x 128 h.
// ---------------------------------------------------------------------------
__global__ __launch_bounds__(HID) void embed_kernel(const float* __restrict__ W,
                                                    const float* __restrict__ b,
                                                    float* __restrict__ out) {
    __shared__ float cs[8][NN];   // reduced counts for this block's 8 rows

    const int t  = threadIdx.x;
    const int i0 = blockIdx.x * 8;

    // Phase A: 36 bins x 2 words (4 rows each) = 72 tasks; 16 independent
    // u32 loads per task (high MLP), packed-u16 accumulation (max 960).
    if (t < NN * 2) {
        const int c    = t >> 1;
        const int half = t & 1;           // rows half*4 .. half*4+3
        const unsigned* gp = g8 + c * HB4 + (i0 >> 2) + half;
        unsigned a01 = 0u, a23 = 0u;
#pragma unroll
        for (int sl = 0; sl < NSL; sl++) {
            const unsigned v = gp[sl * NN * HB4];
            a01 += __byte_perm(v, 0, 0x4140);   // (b0,b1) as u16 pair
            a23 += __byte_perm(v, 0, 0x4342);   // (b2,b3)
        }
        const unsigned self = (c == 3 * GN + 3) ? 1u : 0u;
        const int r0 = half * 4;
        cs[r0 + 0][c] = (float)((a01 & 0xFFFFu) - self);
        cs[r0 + 1][c] = (float)((a01 >> 16)     - self);
        cs[r0 + 2][c] = (float)((a23 & 0xFFFFu) - self);
        cs[r0 + 3][c] = (float)((a23 >> 16)     - self);
    }
    __syncthreads();

    // Phase B: thread = (h pair, row group). h0 = 2*(t%64), rows (t/64)*4..+3.
    const int h0 = (t & 63) * 2;
    const int rg = t >> 6;

    float w[2 * NN];   // W rows h0, h0+1: 72 consecutive floats = 18 float4
    {
        const float4* Wv = (const float4*)(W + h0 * NN);
#pragma unroll
        for (int q = 0; q < 2 * NN / 4; q++) {
            const float4 v = Wv[q];
            w[4 * q + 0] = v.x; w[4 * q + 1] = v.y;
            w[4 * q + 2] = v.z; w[4 * q + 3] = v.w;
        }
    }
    const float bh0 = b[h0];
    const float bh1 = b[h0 + 1];

#pragma unroll
    for (int r = 0; r < 4; r++) {
        const int row = rg * 4 + r;
        float a0 = bh0, a1 = bh1;
#pragma unroll
        for (int c = 0; c < NN; c++) {
            const float v = cs[row][c];        // broadcast LDS -> 2 FMAs
            a0 = fmaf(v, w[c], a0);
            a1 = fmaf(v, w[NN + c], a1);
        }
        *(float2*)&out[(i0 + row) * HID + h0] = make_float2(a0, a1);
    }
}

// ---------------------------------------------------------------------------
// Inputs: 0 hidden_state (unused), 1 obs1 (unused), 2 obs2 [8192,2],
// 3 W [128,36], 4 b [128]. Output fp32 [8192,128].
// ---------------------------------------------------------------------------
extern "C" void kernel_launch(void* const* d_in, const int* in_sizes, int n_in,
                              void* d_out, int out_size) {
    const float* obs2 = (const float*)d_in[2];
    const float* W    = (const float*)d_in[3];
    const float* b    = (const float*)d_in[4];
    float*       out  = (float*)d_out;

    dim3 g1(NPED / RPB, NSL);        // 64 x 16 = 1024 blocks
    count_kernel<<<g1, RPB>>>(obs2);
    embed_kernel<<<NPED / 8, HID>>>(W, b, out);
}